// round 1
// baseline (speedup 1.0000x reference)
#include <cuda_runtime.h>
#include <stdint.h>
#include <stddef.h>

#define NTOK 8192
#define EMB  1024
#define NH   16
#define HD   64

// ---------------- scratch (static device globals; no allocation) ----------------
__device__ float g_q[(size_t)NTOK * EMB];
__device__ float g_k[(size_t)NTOK * EMB];
__device__ float g_v[(size_t)NTOK * EMB];
__device__ float g_x[(size_t)NTOK * EMB];   // attention output, scattered (zero-filled first)
__device__ float g_ln[(size_t)NTOK * EMB];  // layernorm output

// ---------------- helpers ----------------
__device__ __forceinline__ float tf32f(float x) {
    unsigned u;
    asm("cvt.rna.tf32.f32 %0, %1;" : "=r"(u) : "f"(x));
    return __uint_as_float(u);
}
__device__ __forceinline__ unsigned fbits(float x) { return __float_as_uint(x); }

__device__ __forceinline__ void mma8(float c[4], const unsigned a[4], const unsigned b[2]) {
    asm volatile(
        "mma.sync.aligned.m16n8k8.row.col.f32.tf32.tf32.f32 "
        "{%0,%1,%2,%3},{%4,%5,%6,%7},{%8,%9},{%0,%1,%2,%3};\n"
        : "+f"(c[0]), "+f"(c[1]), "+f"(c[2]), "+f"(c[3])
        : "r"(a[0]), "r"(a[1]), "r"(a[2]), "r"(a[3]), "r"(b[0]), "r"(b[1]));
}

// ---------------- zero fill ----------------
__global__ void zero_kernel(float4* p) {
    p[(size_t)blockIdx.x * blockDim.x + threadIdx.x] = make_float4(0.f, 0.f, 0.f, 0.f);
}

// ---------------- GEMM: C[M,N] = A[M,K] @ W[N,K]^T + bias ----------------
// CTA tile 128x128, 8 warps (2x4 grid of 64x32 warp tiles), k-chunk 16, tf32 mma.
__global__ __launch_bounds__(256) void gemm_bias_kernel(
    const float* __restrict__ A, const float* __restrict__ W,
    const float* __restrict__ bias, float* __restrict__ C,
    int M, int Nn, int K)
{
    __shared__ float As[128 * 20];  // [row][k], pitch 20 -> conflict-free frag loads
    __shared__ float Bs[128 * 20];  // [n][k]

    const int bm = blockIdx.y * 128;
    const int bn = blockIdx.x * 128;
    const int tid = threadIdx.x;
    const int lane = tid & 31;
    const int warp = tid >> 5;
    const int wm = (warp & 1) * 64;
    const int wn = (warp >> 1) * 32;

    float acc[4][4][4];
#pragma unroll
    for (int mt = 0; mt < 4; mt++)
#pragma unroll
        for (int nt = 0; nt < 4; nt++)
#pragma unroll
            for (int i = 0; i < 4; i++) acc[mt][nt][i] = 0.f;

    for (int k0 = 0; k0 < K; k0 += 16) {
#pragma unroll
        for (int i = 0; i < 2; i++) {
            int id = tid + i * 256;
            int row = id >> 2;
            int c4 = (id & 3) << 2;
            float4 va = *(const float4*)(A + (size_t)(bm + row) * K + k0 + c4);
            float* d = As + row * 20 + c4;
            d[0] = tf32f(va.x); d[1] = tf32f(va.y); d[2] = tf32f(va.z); d[3] = tf32f(va.w);
            float4 vb = *(const float4*)(W + (size_t)(bn + row) * K + k0 + c4);
            float* e = Bs + row * 20 + c4;
            e[0] = tf32f(vb.x); e[1] = tf32f(vb.y); e[2] = tf32f(vb.z); e[3] = tf32f(vb.w);
        }
        __syncthreads();
#pragma unroll
        for (int kk = 0; kk < 2; kk++) {
            unsigned af[4][4], bf[4][2];
#pragma unroll
            for (int mt = 0; mt < 4; mt++) {
                int r = wm + mt * 16 + (lane >> 2);
                int c = kk * 8 + (lane & 3);
                af[mt][0] = fbits(As[r * 20 + c]);
                af[mt][1] = fbits(As[(r + 8) * 20 + c]);
                af[mt][2] = fbits(As[r * 20 + c + 4]);
                af[mt][3] = fbits(As[(r + 8) * 20 + c + 4]);
            }
#pragma unroll
            for (int nt = 0; nt < 4; nt++) {
                int n = wn + nt * 8 + (lane >> 2);
                int c = kk * 8 + (lane & 3);
                bf[nt][0] = fbits(Bs[n * 20 + c]);
                bf[nt][1] = fbits(Bs[n * 20 + c + 4]);
            }
#pragma unroll
            for (int mt = 0; mt < 4; mt++)
#pragma unroll
                for (int nt = 0; nt < 4; nt++)
                    mma8(acc[mt][nt], af[mt], bf[nt]);
        }
        __syncthreads();
    }

#pragma unroll
    for (int nt = 0; nt < 4; nt++) {
        int c = bn + wn + nt * 8 + ((lane & 3) << 1);
        float b0 = bias[c], b1 = bias[c + 1];
#pragma unroll
        for (int mt = 0; mt < 4; mt++) {
            int r = bm + wm + mt * 16 + (lane >> 2);
            *(float2*)(C + (size_t)r * Nn + c) =
                make_float2(acc[mt][nt][0] + b0, acc[mt][nt][1] + b1);
            *(float2*)(C + (size_t)(r + 8) * Nn + c) =
                make_float2(acc[mt][nt][2] + b0, acc[mt][nt][3] + b1);
        }
    }
}

// ---------------- attention ----------------
// 39 problems: group0 (seg 2048, dil 1) = 4 segs x 6 heads = 24
//              group1 (seg 4096, dil 2) = 2 segs x 5 heads = 10
//              group2 (seg 8192, dil 4) = 1 seg  x 5 heads = 5
// Every problem is dense attention over 2048 slots with head_dim 64.
// Grid: (16 row-blocks, 39 problems). 256 threads, each warp owns 16 query rows.
#define QP 68
#define KP 68
#define VP 72
#define SP 132
#define ATTN_SMEM_BYTES ((128*QP + 128*KP + 128*VP + 128*SP + 3*128) * 4)

__global__ __launch_bounds__(256) void attn_kernel() {
    extern __shared__ float sm[];
    float* Qs   = sm;
    float* Ks   = Qs + 128 * QP;
    float* Vs   = Ks + 128 * KP;
    float* Ss   = Vs + 128 * VP;
    float* rowm = Ss + 128 * SP;
    float* rowl = rowm + 128;
    float* rowa = rowl + 128;

    const int p = blockIdx.y;
    int rate, off, head, segbase;
    if (p < 24)      { rate = 1; off = 0; segbase = (p / 6) * 2048;         head = p % 6; }
    else if (p < 34) { int q = p - 24; rate = 2; off = 1; segbase = (q / 5) * 4096; head = 6 + q % 5; }
    else             { int q = p - 34; rate = 4; off = 2; segbase = 0;             head = 11 + q; }

    const int tid = threadIdx.x;
    const int lane = tid & 31;
    const int warp = tid >> 5;
    const int q0 = blockIdx.x * 128;
    const float scale = 0.125f;  // 1/sqrt(64)

    // load Q tile (scaled, tf32-rounded)
    for (int i = tid; i < 2048; i += 256) {
        int s = i >> 4;
        int c4 = (i & 15) << 2;
        int tok = segbase + off + (q0 + s) * rate;
        const float4 v = *(const float4*)(g_q + ((size_t)tok * NH + head) * HD + c4);
        float* d = Qs + s * QP + c4;
        d[0] = tf32f(v.x * scale); d[1] = tf32f(v.y * scale);
        d[2] = tf32f(v.z * scale); d[3] = tf32f(v.w * scale);
    }
    if (tid < 128) { rowm[tid] = -1e30f; rowl[tid] = 0.f; }
    __syncthreads();

    // Q fragments resident in registers (16 rows per warp, k = 0..63)
    unsigned qf[8][4];
    {
        int r = warp * 16 + (lane >> 2);
#pragma unroll
        for (int kk = 0; kk < 8; kk++) {
            int c = kk * 8 + (lane & 3);
            qf[kk][0] = fbits(Qs[r * QP + c]);
            qf[kk][1] = fbits(Qs[(r + 8) * QP + c]);
            qf[kk][2] = fbits(Qs[r * QP + c + 4]);
            qf[kk][3] = fbits(Qs[(r + 8) * QP + c + 4]);
        }
    }
    float o[8][4];
#pragma unroll
    for (int nt = 0; nt < 8; nt++) { o[nt][0] = o[nt][1] = o[nt][2] = o[nt][3] = 0.f; }

    for (int j0 = 0; j0 < 2048; j0 += 128) {
        __syncthreads();  // previous iteration's PV reads done before overwrite
        for (int i = tid; i < 2048; i += 256) {
            int s = i >> 4;
            int c4 = (i & 15) << 2;
            int tok = segbase + off + (j0 + s) * rate;
            size_t base = ((size_t)tok * NH + head) * HD + c4;
            float4 kv = *(const float4*)(g_k + base);
            float4 vv = *(const float4*)(g_v + base);
            float* dk = Ks + s * KP + c4;
            dk[0] = tf32f(kv.x); dk[1] = tf32f(kv.y); dk[2] = tf32f(kv.z); dk[3] = tf32f(kv.w);
            float* dv = Vs + s * VP + c4;
            dv[0] = tf32f(vv.x); dv[1] = tf32f(vv.y); dv[2] = tf32f(vv.z); dv[3] = tf32f(vv.w);
        }
        __syncthreads();

        // S = (Q*scale) K^T  -> Ss
        {
            int r = warp * 16 + (lane >> 2);
            for (int nt = 0; nt < 16; nt++) {
                float sc4[4] = {0.f, 0.f, 0.f, 0.f};
                int n = nt * 8 + (lane >> 2);
#pragma unroll
                for (int kk = 0; kk < 8; kk++) {
                    unsigned b[2];
                    int c = kk * 8 + (lane & 3);
                    b[0] = fbits(Ks[n * KP + c]);
                    b[1] = fbits(Ks[n * KP + c + 4]);
                    mma8(sc4, qf[kk], b);
                }
                int cc = nt * 8 + ((lane & 3) << 1);
                *(float2*)(Ss + r * SP + cc)       = make_float2(sc4[0], sc4[1]);
                *(float2*)(Ss + (r + 8) * SP + cc) = make_float2(sc4[2], sc4[3]);
            }
        }
        __syncthreads();

        // online softmax: 2 threads per row, 64 cols each
        {
            int r = tid >> 1, half = tid & 1;
            float* srow = Ss + r * SP + half * 64;
            float mx = -1e30f;
#pragma unroll 8
            for (int c = 0; c < 64; c++) mx = fmaxf(mx, srow[c]);
            mx = fmaxf(mx, __shfl_xor_sync(0xffffffffu, mx, 1));
            float mold = rowm[r];
            float mnew = fmaxf(mold, mx);
            float sum = 0.f;
#pragma unroll 8
            for (int c = 0; c < 64; c++) {
                float e = __expf(srow[c] - mnew);
                sum += e;
                srow[c] = tf32f(e);
            }
            sum += __shfl_xor_sync(0xffffffffu, sum, 1);
            if (half == 0) {
                float alpha = __expf(mold - mnew);
                rowa[r] = alpha;
                rowl[r] = rowl[r] * alpha + sum;
                rowm[r] = mnew;
            }
        }
        __syncthreads();

        // rescale O and accumulate O += P V
        {
            int r = warp * 16 + (lane >> 2);
            float a0 = rowa[r], a1 = rowa[r + 8];
#pragma unroll
            for (int nt = 0; nt < 8; nt++) {
                o[nt][0] *= a0; o[nt][1] *= a0; o[nt][2] *= a1; o[nt][3] *= a1;
            }
            for (int kk = 0; kk < 16; kk++) {
                unsigned a[4];
                int c = kk * 8 + (lane & 3);
                a[0] = fbits(Ss[r * SP + c]);
                a[1] = fbits(Ss[(r + 8) * SP + c]);
                a[2] = fbits(Ss[r * SP + c + 4]);
                a[3] = fbits(Ss[(r + 8) * SP + c + 4]);
                int kr = kk * 8 + (lane & 3);
                int nn = (lane >> 2);
#pragma unroll
                for (int nt = 0; nt < 8; nt++) {
                    unsigned b[2];
                    b[0] = fbits(Vs[kr * VP + nt * 8 + nn]);
                    b[1] = fbits(Vs[(kr + 4) * VP + nt * 8 + nn]);
                    mma8(o[nt], a, b);
                }
            }
        }
    }

    // epilogue: divide by l, scatter to g_x
    {
        int r = warp * 16 + (lane >> 2);
        float inv0 = 1.f / rowl[r];
        float inv1 = 1.f / rowl[r + 8];
        int tok0 = segbase + off + (q0 + r) * rate;
        int tok1 = segbase + off + (q0 + r + 8) * rate;
#pragma unroll
        for (int nt = 0; nt < 8; nt++) {
            int c = nt * 8 + ((lane & 3) << 1);
            *(float2*)(g_x + ((size_t)tok0 * NH + head) * HD + c) =
                make_float2(o[nt][0] * inv0, o[nt][1] * inv0);
            *(float2*)(g_x + ((size_t)tok1 * NH + head) * HD + c) =
                make_float2(o[nt][2] * inv1, o[nt][3] * inv1);
        }
    }
}

// ---------------- LayerNorm ----------------
__global__ __launch_bounds__(256) void ln_kernel(
    const float* __restrict__ x_in, float* __restrict__ y_out,
    const float* __restrict__ gam, const float* __restrict__ bet)
{
    __shared__ float red[16];
    const int row = blockIdx.x;
    const int tid = threadIdx.x;
    const int c = tid * 4;
    const float4 xv = *(const float4*)(x_in + (size_t)row * EMB + c);
    float s = xv.x + xv.y + xv.z + xv.w;
    float s2 = xv.x * xv.x + xv.y * xv.y + xv.z * xv.z + xv.w * xv.w;
#pragma unroll
    for (int o = 16; o; o >>= 1) {
        s += __shfl_xor_sync(0xffffffffu, s, o);
        s2 += __shfl_xor_sync(0xffffffffu, s2, o);
    }
    if ((tid & 31) == 0) { red[tid >> 5] = s; red[8 + (tid >> 5)] = s2; }
    __syncthreads();
    if (tid < 32) {
        float a = (tid < 8) ? red[tid] : 0.f;
        float b = (tid < 8) ? red[8 + tid] : 0.f;
#pragma unroll
        for (int o = 4; o; o >>= 1) {
            a += __shfl_xor_sync(0xffffffffu, a, o);
            b += __shfl_xor_sync(0xffffffffu, b, o);
        }
        if (tid == 0) { red[0] = a; red[1] = b; }
    }
    __syncthreads();
    const float mu = red[0] * (1.f / EMB);
    const float var = red[1] * (1.f / EMB) - mu * mu;
    const float rs = rsqrtf(var + 1e-5f);
    const float4 gv = *(const float4*)(gam + c);
    const float4 bv = *(const float4*)(bet + c);
    float4 ov;
    ov.x = (xv.x - mu) * rs * gv.x + bv.x;
    ov.y = (xv.y - mu) * rs * gv.y + bv.y;
    ov.z = (xv.z - mu) * rs * gv.z + bv.z;
    ov.w = (xv.w - mu) * rs * gv.w + bv.w;
    *(float4*)(y_out + (size_t)row * EMB + c) = ov;
}

// ---------------- launch ----------------
extern "C" void kernel_launch(void* const* d_in, const int* in_sizes, int n_in,
                              void* d_out, int out_size)
{
    (void)in_sizes; (void)n_in; (void)out_size;
    const float* query = (const float*)d_in[0];
    const float* key   = (const float*)d_in[1];
    const float* value = (const float*)d_in[2];
    const float* Wq = (const float*)d_in[3];
    const float* bq = (const float*)d_in[4];
    const float* Wk = (const float*)d_in[5];
    const float* bk = (const float*)d_in[6];
    const float* Wv = (const float*)d_in[7];
    const float* bv = (const float*)d_in[8];
    const float* Wo = (const float*)d_in[9];
    const float* bo = (const float*)d_in[10];
    const float* ln_g = (const float*)d_in[11];
    const float* ln_b = (const float*)d_in[12];
    float* out = (float*)d_out;

    float *pq, *pk, *pv, *px, *pln;
    cudaGetSymbolAddress((void**)&pq, g_q);
    cudaGetSymbolAddress((void**)&pk, g_k);
    cudaGetSymbolAddress((void**)&pv, g_v);
    cudaGetSymbolAddress((void**)&px, g_x);
    cudaGetSymbolAddress((void**)&pln, g_ln);

    // zero the scatter buffer (uncovered (token, head) slots must be exactly 0)
    zero_kernel<<<(NTOK * EMB / 4) / 256, 256>>>((float4*)px);

    dim3 ggrid(EMB / 128, NTOK / 128);
    gemm_bias_kernel<<<ggrid, 256>>>(query, Wq, bq, pq, NTOK, EMB, EMB);
    gemm_bias_kernel<<<ggrid, 256>>>(key,   Wk, bk, pk, NTOK, EMB, EMB);
    gemm_bias_kernel<<<ggrid, 256>>>(value, Wv, bv, pv, NTOK, EMB, EMB);

    cudaFuncSetAttribute(attn_kernel, cudaFuncAttributeMaxDynamicSharedMemorySize,
                         ATTN_SMEM_BYTES);
    attn_kernel<<<dim3(16, 39), 256, ATTN_SMEM_BYTES>>>();

    ln_kernel<<<NTOK, 256>>>(px, pln, ln_g, ln_b);

    gemm_bias_kernel<<<ggrid, 256>>>(pln, Wo, bo, out, NTOK, EMB, EMB);
}